// round 14
// baseline (speedup 1.0000x reference)
#include <cuda_runtime.h>
#include <cuda_bf16.h>
#include <cstdint>

#define NN 512
#define NE 16384
#define FULLM 0xffffffffu

// ---- scratch (device globals; no allocations allowed) ----
__device__ __align__(16) int      g_tab[NN * NN];      // eid(i,j); read only where bitmap set
__device__ __align__(16) uint32_t g_bmA[NN * 16];
__device__ __align__(16) uint32_t g_bmB[NN * 16];
__device__ __align__(16) float    g_X[NE * 64];
__device__ __align__(16) float    g_Y[NE * 64];
__device__ __align__(16) uint32_t g_W1f[8 * 8192];     // W1 chunks, bf16 hi/lo frag-major
__device__ __align__(16) uint32_t g_W2f[8 * 4096];     // W2 chunks, bf16 hi/lo frag-major

// ---- helpers ----
__device__ __forceinline__ void splitbf(float v, __nv_bfloat16& hi, __nv_bfloat16& lo) {
    hi = __float2bfloat16(v);
    lo = __float2bfloat16(v - __bfloat162float(hi));
}
__device__ __forceinline__ uint32_t packbf(__nv_bfloat16 l16, __nv_bfloat16 h16) {
    __nv_bfloat162 t = __halves2bfloat162(l16, h16);
    return *reinterpret_cast<uint32_t*>(&t);
}
__device__ __forceinline__ void split_pack2(float v0, float v1,
                                            uint32_t& hiu, uint32_t& lou) {
    __nv_bfloat16 h0, l0, h1, l1;
    splitbf(v0, h0, l0);
    splitbf(v1, h1, l1);
    hiu = packbf(h0, h1);
    lou = packbf(l0, l1);
}
__device__ __forceinline__ void mma16(float* c, uint32_t a0, uint32_t a1,
                                      uint32_t a2, uint32_t a3,
                                      uint32_t b0, uint32_t b1) {
    asm volatile(
        "mma.sync.aligned.m16n8k16.row.col.f32.bf16.bf16.f32 "
        "{%0,%1,%2,%3}, {%4,%5,%6,%7}, {%8,%9}, {%0,%1,%2,%3};"
        : "+f"(c[0]), "+f"(c[1]), "+f"(c[2]), "+f"(c[3])
        : "r"(a0), "r"(a1), "r"(a2), "r"(a3), "r"(b0), "r"(b1));
}
__device__ __forceinline__ uint32_t smem_addr_u32(const void* p) {
    uint32_t a;
    asm("{ .reg .u64 t; cvta.to.shared.u64 t, %1; cvt.u32.u64 %0, t; }"
        : "=r"(a) : "l"(p));
    return a;
}
__device__ __forceinline__ void cp16(uint32_t dst, const void* src) {
    asm volatile("cp.async.cg.shared.global [%0], [%1], 16;"
                 :: "r"(dst), "l"(src) : "memory");
}
__device__ __forceinline__ void cp_commit() {
    asm volatile("cp.async.commit_group;" ::: "memory");
}
template <int N>
__device__ __forceinline__ void cp_wait() {
    asm volatile("cp.async.wait_group %0;" :: "n"(N) : "memory");
}

// =======================================================================
// kernel 0: prep weights (blocks 0-7) + zero bitmaps (blocks 8-39)
// =======================================================================
__global__ void k_prep(const float* __restrict__ W1, const float* __restrict__ W2) {
    int tid = threadIdx.x;
    if (blockIdx.x >= 8) {
        int i = (blockIdx.x - 8) * 256 + tid;
        g_bmA[i] = 0u;
        g_bmB[i] = 0u;
        return;
    }
    int hb = blockIdx.x;
    __nv_bfloat16* p1 = (__nv_bfloat16*)g_W1f;
    __nv_bfloat16* p2 = (__nv_bfloat16*)g_W2f;
    for (int i = tid; i < 64 * 128; i += 256) {
        int h = i >> 7, c = i & 127;
        __nv_bfloat16 hi, lo; splitbf(W1[(hb * 64 + h) * 128 + c], hi, lo);
        int nt = h >> 3, kt = c >> 4;
        int ln = (h & 7) * 4 + ((c & 7) >> 1);
        int reg = (c >> 3) & 1, half = c & 1;
        int base = hb * 8192 + ((nt * 8 + kt) * 32 + ln) * 4;
        p1[(base + reg) * 2 + half] = hi;
        p1[(base + 2 + reg) * 2 + half] = lo;
    }
    for (int i = tid; i < 64 * 64; i += 256) {
        int o = i >> 6, h = i & 63;
        __nv_bfloat16 hi, lo; splitbf(W2[o * 512 + hb * 64 + h], hi, lo);
        int nt = o >> 3, kt = h >> 4;
        int ln = (o & 7) * 4 + ((h & 7) >> 1);
        int reg = (h >> 3) & 1, half = h & 1;
        int base = hb * 4096 + ((nt * 4 + kt) * 32 + ln) * 4;
        p2[(base + reg) * 2 + half] = hi;
        p2[(base + 2 + reg) * 2 + half] = lo;
    }
}

// =======================================================================
// kernel 1: fused scatter (table + bitmaps) + X/Y projections
// =======================================================================
__global__ void k_fused(const int* __restrict__ ei, const float* __restrict__ C,
                        const float* __restrict__ W1, const float* __restrict__ W2) {
    if (blockIdx.x >= 512) {
        int e = (blockIdx.x - 512) * 256 + threadIdx.x;
        int a = ei[e], b = ei[NE + e];
        g_tab[a * NN + b] = e;
        atomicOr(&g_bmA[a * 16 + (b >> 5)], 1u << (b & 31));
        atomicOr(&g_bmB[b * 16 + (a >> 5)], 1u << (a & 31));
        return;
    }
    __shared__ float sC[32 * 65];
    __shared__ float sW1[64 * 65];
    __shared__ float sW2[64 * 65];
    int tid = threadIdx.x;
    for (int i = tid; i < 4096; i += 256) {
        int r = i >> 6, c = i & 63;
        sW1[r * 65 + c] = W1[i];
        sW2[r * 65 + c] = W2[i];
    }
    int e0 = blockIdx.x * 32;
    for (int i = tid; i < 2048; i += 256)
        sC[(i >> 6) * 65 + (i & 63)] = C[e0 * 64 + i];
    __syncthreads();

    int el = tid >> 3, fo = (tid & 7) << 3;
    float ax[8], ay[8];
#pragma unroll
    for (int u = 0; u < 8; u++) { ax[u] = 0.f; ay[u] = 0.f; }
#pragma unroll 4
    for (int c = 0; c < 64; c++) {
        float cv = sC[el * 65 + c];
#pragma unroll
        for (int u = 0; u < 8; u++) {
            ax[u] = fmaf(cv, sW1[(fo + u) * 65 + c], ax[u]);
            ay[u] = fmaf(cv, sW2[(fo + u) * 65 + c], ay[u]);
        }
    }
    float4* px = (float4*)&g_X[(e0 + el) * 64 + fo];
    px[0] = make_float4(ax[0], ax[1], ax[2], ax[3]);
    px[1] = make_float4(ax[4], ax[5], ax[6], ax[7]);
    float4* py = (float4*)&g_Y[(e0 + el) * 64 + fo];
    py[0] = make_float4(ay[0], ay[1], ay[2], ay[3]);
    py[1] = make_float4(ay[4], ay[5], ay[6], ay[7]);
}

// =======================================================================
// kernel 2: fused paths + MLP. 128 blocks x 512 threads (16 warps).
// Paths phase writes M straight into A-fragments in smem (no g_M).
// MMA phase: warp tile 32x16, bf16 hi/lo split x 3 products.
// smem u32: A_hi[8192] A_lo[8192] B1[2x8192] B2[2x4096] H_hi[4096] H_lo[4096]
// =======================================================================
#define U_AHI 0
#define U_ALO 8192
#define U_B1  16384
#define U_B2  32768
#define U_HHI 40960
#define U_HLO 45056
#define SMEMB 196608
#define NTHR 512

__device__ __forceinline__ void a_frag_store(uint32_t* smu, int r, int c,
                                             float v0, float v1) {
    uint32_t hiu, lou;
    split_pack2(v0, v1, hiu, lou);
    int tile = (r >> 4) * 8 + (c >> 4);
    int ln = (r & 7) * 4 + ((c & 7) >> 1);
    int reg = ((r >> 3) & 1) + 2 * ((c >> 3) & 1);
    int u = tile * 128 + ln * 4 + reg;
    smu[U_AHI + u] = hiu;
    smu[U_ALO + u] = lou;
}

__global__ void __launch_bounds__(NTHR, 1)
k_mlp(const int* __restrict__ ei, const float* __restrict__ C,
      float* __restrict__ out) {
    extern __shared__ uint32_t smu[];
    const int tid = threadIdx.x;
    const int wid = tid >> 5, lane = tid & 31;
    const int e0 = blockIdx.x * 128;
    const uint32_t sb = smem_addr_u32(smu);

    // prefetch weight chunk 0 while paths compute
    {
        const uint4* s1 = (const uint4*)&g_W1f[0];
        for (int i = tid; i < 2048; i += NTHR) cp16(sb + U_B1 * 4 + i * 16, s1 + i);
        const uint4* s2 = (const uint4*)&g_W2f[0];
        for (int i = tid; i < 1024; i += NTHR) cp16(sb + U_B2 * 4 + i * 16, s2 + i);
        cp_commit();
    }

    // stage C (cols 0..63) into A-fragments
    for (int i2 = tid; i2 < 4096; i2 += NTHR) {
        int r = i2 >> 5, c = (i2 & 31) * 2;
        float2 t = *(const float2*)&C[(e0 + r) * 64 + c];
        a_frag_store(smu, r, c, t.x, t.y);
    }

    // ---- paths: warp per edge (8 each), M -> A-fragments cols 64..127 ----
#pragma unroll 2
    for (int s = 0; s < 8; s++) {
        int r = wid * 8 + s;
        int e = e0 + r;
        int i = ei[e], j = ei[NE + e];
        uint32_t w = 0;
        if (lane < 16)
            w = g_bmA[i * 16 + lane] & g_bmB[j * 16 + lane];
        unsigned act = __ballot_sync(FULLM, w != 0);
        float a0 = 0.f, a1 = 0.f;
        while (act) {
            int src = __ffs(act) - 1;
            act &= act - 1;
            uint32_t wm = __shfl_sync(FULLM, w, src);
            while (wm) {
                int b = __ffs(wm) - 1;
                wm &= wm - 1;
                int k = src * 32 + b;
                int h1 = g_tab[i * NN + k];
                int h2 = g_tab[k * NN + j];
                a0 = fmaf(g_X[h1 * 64 + lane],      g_Y[h2 * 64 + lane],      a0);
                a1 = fmaf(g_X[h1 * 64 + 32 + lane], g_Y[h2 * 64 + 32 + lane], a1);
            }
        }
        float b0 = __shfl_down_sync(FULLM, a0, 1);
        float b1 = __shfl_down_sync(FULLM, a1, 1);
        if (!(lane & 1)) {
            a_frag_store(smu, r, 64 + lane, a0, b0);
            a_frag_store(smu, r, 96 + lane, a1, b1);
        }
    }
    __syncthreads();   // A fragments complete

    // ---- MMA phase: 16 warps, warp tile 32x16 ----
    const int mw = wid >> 2, nw = wid & 3;
    const int g = lane >> 2, tg = lane & 3;

    float oAcc[2][2][4];
#pragma unroll
    for (int m = 0; m < 2; m++)
#pragma unroll
        for (int n = 0; n < 2; n++)
#pragma unroll
            for (int q = 0; q < 4; q++) oAcc[m][n][q] = 0.f;

#pragma unroll 1
    for (int hb = 0; hb < 8; hb++) {
        const int buf = hb & 1;
        if (hb) __syncthreads();

        if (hb + 1 < 8) {
            const uint4* s1 = (const uint4*)&g_W1f[(hb + 1) * 8192];
            uint32_t d1 = sb + (U_B1 + (buf ^ 1) * 8192) * 4;
            for (int i = tid; i < 2048; i += NTHR) cp16(d1 + i * 16, s1 + i);
            const uint4* s2 = (const uint4*)&g_W2f[(hb + 1) * 4096];
            uint32_t d2 = sb + (U_B2 + (buf ^ 1) * 4096) * 4;
            for (int i = tid; i < 1024; i += NTHR) cp16(d2 + i * 16, s2 + i);
            cp_commit();
            cp_wait<1>();
        } else {
            cp_wait<0>();
        }
        __syncthreads();

        const uint32_t b1o = U_B1 + buf * 8192;
        const uint32_t b2o = U_B2 + buf * 4096;

        // GEMM1: H[128,64] = tmp @ W1chunk^T
        float hAcc[2][2][4];
#pragma unroll
        for (int m = 0; m < 2; m++)
#pragma unroll
            for (int n = 0; n < 2; n++)
#pragma unroll
                for (int q = 0; q < 4; q++) hAcc[m][n][q] = 0.f;

#pragma unroll 2
        for (int kt = 0; kt < 8; kt++) {
            uint4 ah[2], al[2], bb[2];
#pragma unroll
            for (int m = 0; m < 2; m++) {
                int t = (mw * 2 + m) * 8 + kt;
                ah[m] = *(const uint4*)&smu[U_AHI + t * 128 + lane * 4];
                al[m] = *(const uint4*)&smu[U_ALO + t * 128 + lane * 4];
            }
#pragma unroll
            for (int n = 0; n < 2; n++)
                bb[n] = *(const uint4*)&smu[b1o + ((nw * 2 + n) * 8 + kt) * 128 + lane * 4];
#pragma unroll
            for (int m = 0; m < 2; m++)
#pragma unroll
                for (int n = 0; n < 2; n++) {
                    mma16(hAcc[m][n], ah[m].x, ah[m].y, ah[m].z, ah[m].w, bb[n].x, bb[n].y);
                    mma16(hAcc[m][n], al[m].x, al[m].y, al[m].z, al[m].w, bb[n].x, bb[n].y);
                    mma16(hAcc[m][n], ah[m].x, ah[m].y, ah[m].z, ah[m].w, bb[n].z, bb[n].w);
                }
        }

        // epilogue: relu + split, packed uint4 stores
#pragma unroll
        for (int m = 0; m < 2; m++) {
            uint32_t hi4[4], lo4[4];
#pragma unroll
            for (int q = 0; q < 2; q++) {
                float va = fmaxf(hAcc[m][0][2 * q], 0.f);
                float vb = fmaxf(hAcc[m][0][2 * q + 1], 0.f);
                split_pack2(va, vb, hi4[q], lo4[q]);
            }
#pragma unroll
            for (int q = 0; q < 2; q++) {
                float va = fmaxf(hAcc[m][1][2 * q], 0.f);
                float vb = fmaxf(hAcc[m][1][2 * q + 1], 0.f);
                split_pack2(va, vb, hi4[2 + q], lo4[2 + q]);
            }
            int tile = (mw * 2 + m) * 4 + nw;
            *(uint4*)&smu[U_HHI + tile * 128 + lane * 4] =
                make_uint4(hi4[0], hi4[1], hi4[2], hi4[3]);
            *(uint4*)&smu[U_HLO + tile * 128 + lane * 4] =
                make_uint4(lo4[0], lo4[1], lo4[2], lo4[3]);
        }
        __syncthreads();

        // GEMM2: out += H @ W2chunk^T
#pragma unroll
        for (int kt = 0; kt < 4; kt++) {
            uint4 ah[2], al[2], bb[2];
#pragma unroll
            for (int m = 0; m < 2; m++) {
                int t = (mw * 2 + m) * 4 + kt;
                ah[m] = *(const uint4*)&smu[U_HHI + t * 128 + lane * 4];
                al[m] = *(const uint4*)&smu[U_HLO + t * 128 + lane * 4];
            }
#pragma unroll
            for (int n = 0; n < 2; n++)
                bb[n] = *(const uint4*)&smu[b2o + ((nw * 2 + n) * 4 + kt) * 128 + lane * 4];
#pragma unroll
            for (int m = 0; m < 2; m++)
#pragma unroll
                for (int n = 0; n < 2; n++) {
                    mma16(oAcc[m][n], ah[m].x, ah[m].y, ah[m].z, ah[m].w, bb[n].x, bb[n].y);
                    mma16(oAcc[m][n], al[m].x, al[m].y, al[m].z, al[m].w, bb[n].x, bb[n].y);
                    mma16(oAcc[m][n], ah[m].x, ah[m].y, ah[m].z, ah[m].w, bb[n].z, bb[n].w);
                }
        }
    }

    // ---- write out ----
#pragma unroll
    for (int m = 0; m < 2; m++) {
        int Rb = mw * 32 + m * 16 + g;
#pragma unroll
        for (int n = 0; n < 2; n++) {
            int Ob = (nw * 2 + n) * 8 + 2 * tg;
            *(float2*)&out[(e0 + Rb) * 64 + Ob] =
                make_float2(oAcc[m][n][0], oAcc[m][n][1]);
            *(float2*)&out[(e0 + Rb + 8) * 64 + Ob] =
                make_float2(oAcc[m][n][2], oAcc[m][n][3]);
        }
    }
}

__global__ void k_nop() {}

// =======================================================================
extern "C" void kernel_launch(void* const* d_in, const int* in_sizes, int n_in,
                              void* d_out, int out_size) {
    const int*   ei   = (const int*)  d_in[0];
    const float* C    = (const float*)d_in[1];
    // d_in[2] = batch_node (unused numerically)
    const float* W_L1 = (const float*)d_in[3];
    const float* W_L2 = (const float*)d_in[4];
    const float* Wm1  = (const float*)d_in[5];
    const float* Wm2  = (const float*)d_in[6];
    float* out = (float*)d_out;

    cudaFuncSetAttribute(k_mlp, cudaFuncAttributeMaxDynamicSharedMemorySize, SMEMB);

    k_prep<<<40, 256>>>(Wm1, Wm2);                       // weights + bitmap zero
    k_fused<<<512 + NE / 256, 256>>>(ei, C, W_L1, W_L2);
    k_nop<<<1, 32>>>();                                  // keep k_mlp at launch slot 4
    k_mlp<<<NE / 128, NTHR, SMEMB>>>(ei, C, out);
    k_nop<<<1, 32>>>();
    k_nop<<<1, 32>>>();
}

// round 15
// speedup vs baseline: 1.0478x; 1.0478x over previous
#include <cuda_runtime.h>
#include <cuda_bf16.h>
#include <cstdint>

#define NN 512
#define NE 16384
#define FULLM 0xffffffffu

// ---- scratch (device globals; no allocations allowed) ----
__device__ __align__(16) int      g_tab[NN * NN];      // eid(i,j); read only where bitmap set
__device__ __align__(16) uint32_t g_bmA[NN * 16];
__device__ __align__(16) uint32_t g_bmB[NN * 16];
__device__ __align__(16) float    g_X[NE * 64];
__device__ __align__(16) float    g_Y[NE * 64];
__device__ __align__(16) float    g_M[NE * 64];
__device__ __align__(16) uint32_t g_W1f[8 * 8192];     // W1 chunks, bf16 hi/lo frag-major
__device__ __align__(16) uint32_t g_W2f[8 * 4096];     // W2 chunks, bf16 hi/lo frag-major

// ---- helpers ----
__device__ __forceinline__ void splitbf(float v, __nv_bfloat16& hi, __nv_bfloat16& lo) {
    hi = __float2bfloat16(v);
    lo = __float2bfloat16(v - __bfloat162float(hi));
}
__device__ __forceinline__ uint32_t packbf(__nv_bfloat16 l16, __nv_bfloat16 h16) {
    __nv_bfloat162 t = __halves2bfloat162(l16, h16);
    return *reinterpret_cast<uint32_t*>(&t);
}
__device__ __forceinline__ void split_pack2(float v0, float v1,
                                            uint32_t& hiu, uint32_t& lou) {
    __nv_bfloat16 h0, l0, h1, l1;
    splitbf(v0, h0, l0);
    splitbf(v1, h1, l1);
    hiu = packbf(h0, h1);
    lou = packbf(l0, l1);
}
__device__ __forceinline__ void mma16(float* c, uint32_t a0, uint32_t a1,
                                      uint32_t a2, uint32_t a3,
                                      uint32_t b0, uint32_t b1) {
    asm volatile(
        "mma.sync.aligned.m16n8k16.row.col.f32.bf16.bf16.f32 "
        "{%0,%1,%2,%3}, {%4,%5,%6,%7}, {%8,%9}, {%0,%1,%2,%3};"
        : "+f"(c[0]), "+f"(c[1]), "+f"(c[2]), "+f"(c[3])
        : "r"(a0), "r"(a1), "r"(a2), "r"(a3), "r"(b0), "r"(b1));
}
__device__ __forceinline__ uint32_t smem_addr_u32(const void* p) {
    uint32_t a;
    asm("{ .reg .u64 t; cvta.to.shared.u64 t, %1; cvt.u32.u64 %0, t; }"
        : "=r"(a) : "l"(p));
    return a;
}
__device__ __forceinline__ void cp16(uint32_t dst, const void* src) {
    asm volatile("cp.async.cg.shared.global [%0], [%1], 16;"
                 :: "r"(dst), "l"(src) : "memory");
}
__device__ __forceinline__ void cp_commit() {
    asm volatile("cp.async.commit_group;" ::: "memory");
}
template <int N>
__device__ __forceinline__ void cp_wait() {
    asm volatile("cp.async.wait_group %0;" :: "n"(N) : "memory");
}

// =======================================================================
// kernel 0: prep weights (blocks 0-7) + zero bitmaps (blocks 8-39)
// =======================================================================
__global__ void k_prep(const float* __restrict__ W1, const float* __restrict__ W2) {
    int tid = threadIdx.x;
    if (blockIdx.x >= 8) {
        int i = (blockIdx.x - 8) * 256 + tid;
        g_bmA[i] = 0u;
        g_bmB[i] = 0u;
        return;
    }
    int hb = blockIdx.x;
    __nv_bfloat16* p1 = (__nv_bfloat16*)g_W1f;
    __nv_bfloat16* p2 = (__nv_bfloat16*)g_W2f;
    for (int i = tid; i < 64 * 128; i += 256) {
        int h = i >> 7, c = i & 127;
        __nv_bfloat16 hi, lo; splitbf(W1[(hb * 64 + h) * 128 + c], hi, lo);
        int nt = h >> 3, kt = c >> 4;
        int ln = (h & 7) * 4 + ((c & 7) >> 1);
        int reg = (c >> 3) & 1, half = c & 1;
        int base = hb * 8192 + ((nt * 8 + kt) * 32 + ln) * 4;
        p1[(base + reg) * 2 + half] = hi;
        p1[(base + 2 + reg) * 2 + half] = lo;
    }
    for (int i = tid; i < 64 * 64; i += 256) {
        int o = i >> 6, h = i & 63;
        __nv_bfloat16 hi, lo; splitbf(W2[o * 512 + hb * 64 + h], hi, lo);
        int nt = o >> 3, kt = h >> 4;
        int ln = (o & 7) * 4 + ((h & 7) >> 1);
        int reg = (h >> 3) & 1, half = h & 1;
        int base = hb * 4096 + ((nt * 4 + kt) * 32 + ln) * 4;
        p2[(base + reg) * 2 + half] = hi;
        p2[(base + 2 + reg) * 2 + half] = lo;
    }
}

// =======================================================================
// kernel 1: fused scatter (table + bitmaps) + X/Y projections
// =======================================================================
__global__ void k_fused(const int* __restrict__ ei, const float* __restrict__ C,
                        const float* __restrict__ W1, const float* __restrict__ W2) {
    if (blockIdx.x >= 512) {
        int e = (blockIdx.x - 512) * 256 + threadIdx.x;
        int a = ei[e], b = ei[NE + e];
        g_tab[a * NN + b] = e;
        atomicOr(&g_bmA[a * 16 + (b >> 5)], 1u << (b & 31));
        atomicOr(&g_bmB[b * 16 + (a >> 5)], 1u << (a & 31));
        return;
    }
    __shared__ float sC[32 * 65];
    __shared__ float sW1[64 * 65];
    __shared__ float sW2[64 * 65];
    int tid = threadIdx.x;
    for (int i = tid; i < 4096; i += 256) {
        int r = i >> 6, c = i & 63;
        sW1[r * 65 + c] = W1[i];
        sW2[r * 65 + c] = W2[i];
    }
    int e0 = blockIdx.x * 32;
    for (int i = tid; i < 2048; i += 256)
        sC[(i >> 6) * 65 + (i & 63)] = C[e0 * 64 + i];
    __syncthreads();

    int el = tid >> 3, fo = (tid & 7) << 3;
    float ax[8], ay[8];
#pragma unroll
    for (int u = 0; u < 8; u++) { ax[u] = 0.f; ay[u] = 0.f; }
#pragma unroll 4
    for (int c = 0; c < 64; c++) {
        float cv = sC[el * 65 + c];
#pragma unroll
        for (int u = 0; u < 8; u++) {
            ax[u] = fmaf(cv, sW1[(fo + u) * 65 + c], ax[u]);
            ay[u] = fmaf(cv, sW2[(fo + u) * 65 + c], ay[u]);
        }
    }
    float4* px = (float4*)&g_X[(e0 + el) * 64 + fo];
    px[0] = make_float4(ax[0], ax[1], ax[2], ax[3]);
    px[1] = make_float4(ax[4], ax[5], ax[6], ax[7]);
    float4* py = (float4*)&g_Y[(e0 + el) * 64 + fo];
    py[0] = make_float4(ay[0], ay[1], ay[2], ay[3]);
    py[1] = make_float4(ay[4], ay[5], ay[6], ay[7]);
}

// =======================================================================
// kernel 2: sparse 2-path accumulation via bitmap intersection
// =======================================================================
__global__ void k_paths(const int* __restrict__ ei) {
    int warp = (blockIdx.x * blockDim.x + threadIdx.x) >> 5;
    int lane = threadIdx.x & 31;
    int i = ei[warp];
    int j = ei[NE + warp];
    uint32_t w = 0;
    if (lane < 16)
        w = g_bmA[i * 16 + lane] & g_bmB[j * 16 + lane];
    unsigned act = __ballot_sync(FULLM, w != 0);
    float a0 = 0.f, a1 = 0.f;
    while (act) {
        int src = __ffs(act) - 1;
        act &= act - 1;
        uint32_t wm = __shfl_sync(FULLM, w, src);
        while (wm) {
            int b = __ffs(wm) - 1;
            wm &= wm - 1;
            int k = src * 32 + b;
            int h1 = g_tab[i * NN + k];   // broadcast load
            int h2 = g_tab[k * NN + j];   // broadcast load
            a0 = fmaf(g_X[h1 * 64 + lane],      g_Y[h2 * 64 + lane],      a0);
            a1 = fmaf(g_X[h1 * 64 + 32 + lane], g_Y[h2 * 64 + 32 + lane], a1);
        }
    }
    g_M[warp * 64 + lane] = a0;
    g_M[warp * 64 + 32 + lane] = a1;
}

// =======================================================================
// kernel 3: MLP via mma.sync bf16 m16n8k16, 2-way split x 3 products
// Block = 128 edges, 256 threads (8 warps: mw=wid>>1, nw=wid&1).
// NEW vs R12: A fragments (hi+lo) loaded ONCE into registers and reused
// across all 8 hidden chunks -> GEMM1 shared-memory traffic halved.
// smem u32: A_hi[8192] A_lo[8192] B1[2x8192] B2[2x4096] H_hi[4096] H_lo[4096]
// =======================================================================
#define U_AHI 0
#define U_ALO 8192
#define U_B1  16384
#define U_B2  32768
#define U_HHI 40960
#define U_HLO 45056
#define SMEMB 196608

__global__ void __launch_bounds__(256, 1)
k_mlp(const float* __restrict__ C, float* __restrict__ out) {
    extern __shared__ uint32_t smu[];
    const int tid = threadIdx.x;
    const int wid = tid >> 5, lane = tid & 31;
    const int mw = wid >> 1, nw = wid & 1;
    const int g = lane >> 2, tg = lane & 3;
    const int e0 = blockIdx.x * 128;
    const uint32_t sb = smem_addr_u32(smu);

    // ---- prefetch weight chunk 0 into buffer 0 ----
    {
        const uint4* s1 = (const uint4*)&g_W1f[0];
        for (int i = tid; i < 2048; i += 256)
            cp16(sb + U_B1 * 4 + i * 16, s1 + i);
        const uint4* s2 = (const uint4*)&g_W2f[0];
        for (int i = tid; i < 1024; i += 256)
            cp16(sb + U_B2 * 4 + i * 16, s2 + i);
        cp_commit();
    }

    // ---- stage A = [C|M] as bf16 hi/lo, A-fragment-major, packed u32 ----
    for (int i2 = tid; i2 < 8192; i2 += 256) {
        int r = i2 >> 6, c = (i2 & 63) * 2;
        float2 t = (c < 64) ? *(const float2*)&C[(e0 + r) * 64 + c]
                            : *(const float2*)&g_M[(e0 + r) * 64 + (c - 64)];
        uint32_t hiu, lou;
        split_pack2(t.x, t.y, hiu, lou);
        int tile = (r >> 4) * 8 + (c >> 4);
        int ln = (r & 7) * 4 + ((c & 7) >> 1);
        int reg = ((r >> 3) & 1) + 2 * ((c >> 3) & 1);
        int u = tile * 128 + ln * 4 + reg;
        smu[U_AHI + u] = hiu;
        smu[U_ALO + u] = lou;
    }
    __syncthreads();

    // ---- load this warp's A fragments into registers (reused x8 chunks) ----
    uint4 rAh[2][8], rAl[2][8];
#pragma unroll
    for (int m = 0; m < 2; m++)
#pragma unroll
        for (int kt = 0; kt < 8; kt++) {
            int t = (mw * 2 + m) * 8 + kt;
            rAh[m][kt] = *(const uint4*)&smu[U_AHI + t * 128 + lane * 4];
            rAl[m][kt] = *(const uint4*)&smu[U_ALO + t * 128 + lane * 4];
        }

    float oAcc[2][4][4];
#pragma unroll
    for (int m = 0; m < 2; m++)
#pragma unroll
        for (int n = 0; n < 4; n++)
#pragma unroll
            for (int q = 0; q < 4; q++) oAcc[m][n][q] = 0.f;

#pragma unroll 1
    for (int hb = 0; hb < 8; hb++) {
        const int buf = hb & 1;
        if (hb) __syncthreads();  // prev GEMM2 done reading its weight buf + H

        // prefetch next chunk into the other buffer
        if (hb + 1 < 8) {
            const uint4* s1 = (const uint4*)&g_W1f[(hb + 1) * 8192];
            uint32_t d1 = sb + (U_B1 + (buf ^ 1) * 8192) * 4;
            for (int i = tid; i < 2048; i += 256) cp16(d1 + i * 16, s1 + i);
            const uint4* s2 = (const uint4*)&g_W2f[(hb + 1) * 4096];
            uint32_t d2 = sb + (U_B2 + (buf ^ 1) * 4096) * 4;
            for (int i = tid; i < 1024; i += 256) cp16(d2 + i * 16, s2 + i);
            cp_commit();
            cp_wait<1>();   // current chunk's group complete
        } else {
            cp_wait<0>();
        }
        __syncthreads();    // weights visible to all

        const uint32_t b1o = U_B1 + buf * 8192;
        const uint32_t b2o = U_B2 + buf * 4096;

        // ---- GEMM1: H[128,64] = tmp[128,128] @ W1chunk^T (A from registers) ----
        float hAcc[2][4][4];
#pragma unroll
        for (int m = 0; m < 2; m++)
#pragma unroll
            for (int n = 0; n < 4; n++)
#pragma unroll
                for (int q = 0; q < 4; q++) hAcc[m][n][q] = 0.f;

#pragma unroll 2
        for (int kt = 0; kt < 8; kt++) {
            uint4 bb[4];
#pragma unroll
            for (int n = 0; n < 4; n++)
                bb[n] = *(const uint4*)&smu[b1o + ((nw * 4 + n) * 8 + kt) * 128 + lane * 4];
#pragma unroll
            for (int m = 0; m < 2; m++) {
                const uint4 ah = rAh[m][kt];
                const uint4 al = rAl[m][kt];
#pragma unroll
                for (int n = 0; n < 4; n++) {
                    mma16(hAcc[m][n], ah.x, ah.y, ah.z, ah.w, bb[n].x, bb[n].y);
                    mma16(hAcc[m][n], al.x, al.y, al.z, al.w, bb[n].x, bb[n].y);
                    mma16(hAcc[m][n], ah.x, ah.y, ah.z, ah.w, bb[n].z, bb[n].w);
                }
            }
        }

        // ---- epilogue: relu + split, packed uint4 stores (conflict-free) ----
#pragma unroll
        for (int m = 0; m < 2; m++) {
#pragma unroll
            for (int kp = 0; kp < 2; kp++) {
                int n0 = kp * 2, n1 = kp * 2 + 1;
                uint32_t hi4[4], lo4[4];
#pragma unroll
                for (int q = 0; q < 2; q++) {   // n0: regs 0,1
                    float va = fmaxf(hAcc[m][n0][2 * q], 0.f);
                    float vb = fmaxf(hAcc[m][n0][2 * q + 1], 0.f);
                    split_pack2(va, vb, hi4[q], lo4[q]);
                }
#pragma unroll
                for (int q = 0; q < 2; q++) {   // n1: regs 2,3
                    float va = fmaxf(hAcc[m][n1][2 * q], 0.f);
                    float vb = fmaxf(hAcc[m][n1][2 * q + 1], 0.f);
                    split_pack2(va, vb, hi4[2 + q], lo4[2 + q]);
                }
                int tile = (mw * 2 + m) * 4 + (nw * 2 + kp);
                *(uint4*)&smu[U_HHI + tile * 128 + lane * 4] =
                    make_uint4(hi4[0], hi4[1], hi4[2], hi4[3]);
                *(uint4*)&smu[U_HLO + tile * 128 + lane * 4] =
                    make_uint4(lo4[0], lo4[1], lo4[2], lo4[3]);
            }
        }
        __syncthreads();

        // ---- GEMM2: out[128,64] += H[128,64] @ W2chunk^T ----
#pragma unroll
        for (int kt = 0; kt < 4; kt++) {
            uint4 ah[2], al[2], bb[4];
#pragma unroll
            for (int m = 0; m < 2; m++) {
                int t = (mw * 2 + m) * 4 + kt;
                ah[m] = *(const uint4*)&smu[U_HHI + t * 128 + lane * 4];
                al[m] = *(const uint4*)&smu[U_HLO + t * 128 + lane * 4];
            }
#pragma unroll
            for (int n = 0; n < 4; n++)
                bb[n] = *(const uint4*)&smu[b2o + ((nw * 4 + n) * 4 + kt) * 128 + lane * 4];
#pragma unroll
            for (int m = 0; m < 2; m++)
#pragma unroll
                for (int n = 0; n < 4; n++) {
                    mma16(oAcc[m][n], ah[m].x, ah[m].y, ah[m].z, ah[m].w, bb[n].x, bb[n].y);
                    mma16(oAcc[m][n], al[m].x, al[m].y, al[m].z, al[m].w, bb[n].x, bb[n].y);
                    mma16(oAcc[m][n], ah[m].x, ah[m].y, ah[m].z, ah[m].w, bb[n].z, bb[n].w);
                }
        }
    }

    // ---- write out ----
#pragma unroll
    for (int m = 0; m < 2; m++) {
        int Rb = mw * 32 + m * 16 + g;
#pragma unroll
        for (int n = 0; n < 4; n++) {
            int Ob = (nw * 4 + n) * 8 + 2 * tg;
            *(float2*)&out[(e0 + Rb) * 64 + Ob] =
                make_float2(oAcc[m][n][0], oAcc[m][n][1]);
            *(float2*)&out[(e0 + Rb + 8) * 64 + Ob] =
                make_float2(oAcc[m][n][2], oAcc[m][n][3]);
        }
    }
}

__global__ void k_nop() {}

// =======================================================================
extern "C" void kernel_launch(void* const* d_in, const int* in_sizes, int n_in,
                              void* d_out, int out_size) {
    const int*   ei   = (const int*)  d_in[0];
    const float* C    = (const float*)d_in[1];
    // d_in[2] = batch_node (unused numerically)
    const float* W_L1 = (const float*)d_in[3];
    const float* W_L2 = (const float*)d_in[4];
    const float* Wm1  = (const float*)d_in[5];
    const float* Wm2  = (const float*)d_in[6];
    float* out = (float*)d_out;

    cudaFuncSetAttribute(k_mlp, cudaFuncAttributeMaxDynamicSharedMemorySize, SMEMB);

    k_prep<<<40, 256>>>(Wm1, Wm2);                       // weights + bitmap zero
    k_fused<<<512 + NE / 256, 256>>>(ei, C, W_L1, W_L2);
    k_paths<<<NE / 8, 256>>>(ei);
    k_mlp<<<NE / 128, 256, SMEMB>>>(C, out);
    k_nop<<<1, 32>>>();
    k_nop<<<1, 32>>>();
}